// round 1
// baseline (speedup 1.0000x reference)
#include <cuda_runtime.h>
#include <cstddef>

#define GRID3 256
#define NVOX  (256*256*256)
#define SEG   64

// 64 MiB scratch volume (static device global: allowed, no allocation)
__device__ float g_vol[NVOX];

// ---------------------------------------------------------------------------
// Scatter: atomicAdd feats into the dense volume. coords are (d,h,w) in [0,256)
// ---------------------------------------------------------------------------
__global__ void scatter_kernel(const float* __restrict__ feats,
                               const int* __restrict__ coords,
                               int n)
{
    int i = blockIdx.x * blockDim.x + threadIdx.x;
    if (i >= n) return;
    int d = coords[3 * i + 0];
    int h = coords[3 * i + 1];
    int w = coords[3 * i + 2];
    size_t idx = ((size_t)d << 16) | ((size_t)h << 8) | (size_t)w;
    atomicAdd(&g_vol[idx], feats[i]);
}

// ---------------------------------------------------------------------------
// Box blur along W (innermost, contiguous). One block = one 256-float row.
// ---------------------------------------------------------------------------
__global__ void blur_w_kernel(const float* __restrict__ in,
                              float* __restrict__ out)
{
    __shared__ float s[GRID3];
    size_t row = (size_t)blockIdx.x << 8;   // 65536 rows
    int x = threadIdx.x;
    s[x] = in[row + x];
    __syncthreads();
    float sum = 0.f;
#pragma unroll
    for (int k = -2; k <= 2; k++) {
        int xx = x + k;
        if (xx >= 0 && xx < GRID3) sum += s[xx];
    }
    out[row + x] = sum;
}

// ---------------------------------------------------------------------------
// Box blur along H. Thread = fixed (d, w), slides a 5-register window over a
// 64-long h-segment. Loads coalesced across w (threadIdx.x).
// ---------------------------------------------------------------------------
__global__ void blur_h_kernel(const float* __restrict__ in,
                              float* __restrict__ out)
{
    int w  = threadIdx.x;          // 0..255
    int d  = blockIdx.x;           // 0..255
    int h0 = blockIdx.y * SEG;     // 0,64,128,192

    const float* p = in  + ((size_t)d << 16) + (size_t)w;
    float*       q = out + ((size_t)d << 16) + (size_t)w;

    float v0 = (h0 - 2 >= 0)    ? p[(size_t)(h0 - 2) << 8] : 0.f;
    float v1 = (h0 - 1 >= 0)    ? p[(size_t)(h0 - 1) << 8] : 0.f;
    float v2 =                    p[(size_t)(h0    ) << 8];
    float v3 = (h0 + 1 < GRID3) ? p[(size_t)(h0 + 1) << 8] : 0.f;

#pragma unroll 8
    for (int h = h0; h < h0 + SEG; h++) {
        float v4 = (h + 2 < GRID3) ? p[(size_t)(h + 2) << 8] : 0.f;
        q[(size_t)h << 8] = ((v0 + v1) + (v2 + v3)) + v4;
        v0 = v1; v1 = v2; v2 = v3; v3 = v4;
    }
}

// ---------------------------------------------------------------------------
// Box blur along D. Thread = fixed (h, w), slides over a 64-long d-segment.
// Loads coalesced across w.
// ---------------------------------------------------------------------------
__global__ void blur_d_kernel(const float* __restrict__ in,
                              float* __restrict__ out)
{
    int w  = threadIdx.x;          // 0..255
    int h  = blockIdx.x;           // 0..255
    int d0 = blockIdx.y * SEG;     // 0,64,128,192

    const float* p = in  + ((size_t)h << 8) + (size_t)w;
    float*       q = out + ((size_t)h << 8) + (size_t)w;

    float v0 = (d0 - 2 >= 0)    ? p[(size_t)(d0 - 2) << 16] : 0.f;
    float v1 = (d0 - 1 >= 0)    ? p[(size_t)(d0 - 1) << 16] : 0.f;
    float v2 =                    p[(size_t)(d0    ) << 16];
    float v3 = (d0 + 1 < GRID3) ? p[(size_t)(d0 + 1) << 16] : 0.f;

#pragma unroll 8
    for (int d = d0; d < d0 + SEG; d++) {
        float v4 = (d + 2 < GRID3) ? p[(size_t)(d + 2) << 16] : 0.f;
        q[(size_t)d << 16] = ((v0 + v1) + (v2 + v3)) + v4;
        v0 = v1; v1 = v2; v2 = v3; v3 = v4;
    }
}

// ---------------------------------------------------------------------------
// Launch: memset vol -> scatter -> blurW (vol->out) -> blurH (out->vol)
//         -> blurD (vol->out)
// All default-stream, graph-capturable, allocation-free.
// ---------------------------------------------------------------------------
extern "C" void kernel_launch(void* const* d_in, const int* in_sizes, int n_in,
                              void* d_out, int out_size)
{
    const float* feats  = (const float*)d_in[0];
    const int*   coords = (const int*)d_in[1];
    int n = in_sizes[0];
    float* out = (float*)d_out;

    float* vol = nullptr;
    cudaGetSymbolAddress((void**)&vol, g_vol);

    cudaMemsetAsync(vol, 0, (size_t)NVOX * sizeof(float));

    scatter_kernel<<<(n + 255) / 256, 256>>>(feats, coords, n);

    blur_w_kernel<<<GRID3 * GRID3, GRID3>>>(vol, out);

    dim3 gridH(GRID3, GRID3 / SEG);
    blur_h_kernel<<<gridH, GRID3>>>(out, vol);

    dim3 gridD(GRID3, GRID3 / SEG);
    blur_d_kernel<<<gridD, GRID3>>>(vol, out);
}

// round 2
// speedup vs baseline: 1.5613x; 1.5613x over previous
#include <cuda_runtime.h>
#include <cstddef>

#define GRID3 256
#define NVOX  (256*256*256)
#define SEG   64
#define HT    32           // h-tile rows per CTA in fused WH pass
#define HROWS (HT + 4)     // with halo
#define WPAD  260          // 256 + 2 zero-pad each side

// Static device scratch (allowed; no allocation)
__device__ float g_vol[NVOX];
__device__ float g_tmp[NVOX];

// ---------------------------------------------------------------------------
// Scatter: atomicAdd feats into the dense volume. coords are (d,h,w) in [0,256)
// ---------------------------------------------------------------------------
__global__ void scatter_kernel(const float* __restrict__ feats,
                               const int* __restrict__ coords,
                               int n)
{
    int i = blockIdx.x * blockDim.x + threadIdx.x;
    if (i >= n) return;
    int d = coords[3 * i + 0];
    int h = coords[3 * i + 1];
    int w = coords[3 * i + 2];
    size_t idx = ((size_t)d << 16) | ((size_t)h << 8) | (size_t)w;
    atomicAdd(&g_vol[idx], feats[i]);
}

// ---------------------------------------------------------------------------
// Fused W+H box blur. CTA = (d, h-tile of HT rows). Loads HROWS raw rows
// (zero-padded in W) into smem; each thread (one w column) slides a 5-reg
// window down H, computing the 5-tap W-sum when a row enters the window.
// ---------------------------------------------------------------------------
__global__ __launch_bounds__(256) void blur_wh_kernel(const float* __restrict__ in,
                                                      float* __restrict__ out)
{
    __shared__ float raw[HROWS][WPAD];

    int w  = threadIdx.x;               // 0..255
    int d  = blockIdx.x;                // 0..255
    int h0 = blockIdx.y * HT;           // 0,32,...,224

    // Zero the W pads (cols 0,1 and 258,259)
    if (w < 2) {
#pragma unroll
        for (int r = 0; r < HROWS; r++) raw[r][w] = 0.f;
    } else if (w >= 254) {
#pragma unroll
        for (int r = 0; r < HROWS; r++) raw[r][w + 4] = 0.f;
    }

    // Load HROWS raw rows (h = h0-2 .. h0+HT+1), zero outside volume
    const float* plane = in + ((size_t)d << 16);
#pragma unroll
    for (int r = 0; r < HROWS; r++) {
        int h = h0 - 2 + r;
        raw[r][w + 2] = (h >= 0 && h < GRID3) ? plane[((size_t)h << 8) + w] : 0.f;
    }
    __syncthreads();

    // 5-tap W sum for row r at column w (data lives at col w+2)
#define WSUM(r) (((raw[r][w] + raw[r][w + 1]) + (raw[r][w + 2] + raw[r][w + 3])) + raw[r][w + 4])

    float v0 = WSUM(0);
    float v1 = WSUM(1);
    float v2 = WSUM(2);
    float v3 = WSUM(3);

    float* oplane = out + ((size_t)d << 16);
#pragma unroll 8
    for (int i = 0; i < HT; i++) {
        float v4 = WSUM(i + 4);
        oplane[((size_t)(h0 + i) << 8) + w] = ((v0 + v1) + (v2 + v3)) + v4;
        v0 = v1; v1 = v2; v2 = v3; v3 = v4;
    }
#undef WSUM
}

// ---------------------------------------------------------------------------
// Box blur along D. Thread = fixed (h, w), slides over a 64-long d-segment.
// Loads coalesced across w.
// ---------------------------------------------------------------------------
__global__ __launch_bounds__(256) void blur_d_kernel(const float* __restrict__ in,
                                                     float* __restrict__ out)
{
    int w  = threadIdx.x;          // 0..255
    int h  = blockIdx.x;           // 0..255
    int d0 = blockIdx.y * SEG;     // 0,64,128,192

    const float* p = in  + ((size_t)h << 8) + (size_t)w;
    float*       q = out + ((size_t)h << 8) + (size_t)w;

    float v0 = (d0 - 2 >= 0)    ? p[(size_t)(d0 - 2) << 16] : 0.f;
    float v1 = (d0 - 1 >= 0)    ? p[(size_t)(d0 - 1) << 16] : 0.f;
    float v2 =                    p[(size_t)(d0    ) << 16];
    float v3 = (d0 + 1 < GRID3) ? p[(size_t)(d0 + 1) << 16] : 0.f;

#pragma unroll 8
    for (int d = d0; d < d0 + SEG; d++) {
        float v4 = (d + 2 < GRID3) ? p[(size_t)(d + 2) << 16] : 0.f;
        q[(size_t)d << 16] = ((v0 + v1) + (v2 + v3)) + v4;
        v0 = v1; v1 = v2; v2 = v3; v3 = v4;
    }
}

// ---------------------------------------------------------------------------
// Launch: memset vol -> scatter (->vol) -> fused WH (vol->tmp)
//         -> blur D (tmp->d_out)
// All default-stream, graph-capturable, allocation-free.
// ---------------------------------------------------------------------------
extern "C" void kernel_launch(void* const* d_in, const int* in_sizes, int n_in,
                              void* d_out, int out_size)
{
    const float* feats  = (const float*)d_in[0];
    const int*   coords = (const int*)d_in[1];
    int n = in_sizes[0];
    float* out = (float*)d_out;

    float* vol = nullptr;
    float* tmp = nullptr;
    cudaGetSymbolAddress((void**)&vol, g_vol);
    cudaGetSymbolAddress((void**)&tmp, g_tmp);

    cudaMemsetAsync(vol, 0, (size_t)NVOX * sizeof(float));

    scatter_kernel<<<(n + 255) / 256, 256>>>(feats, coords, n);

    dim3 gridWH(GRID3, GRID3 / HT);
    blur_wh_kernel<<<gridWH, GRID3>>>(vol, tmp);

    dim3 gridD(GRID3, GRID3 / SEG);
    blur_d_kernel<<<gridD, GRID3>>>(tmp, out);
}